// round 15
// baseline (speedup 1.0000x reference)
#include <cuda_runtime.h>

#define N_MAX 50000
#define E_MAX 800000
#define HD 128
#define NH 8

// ---- scratch (device globals; no allocation allowed) ----
__device__ float g_hf[N_MAX * HD];      // nfeat @ W_fc
__device__ float g_el[N_MAX * NH];
__device__ float g_er[N_MAX * NH];
__device__ float g_denom[N_MAX * NH];
__device__ float g_indeg[N_MAX];
__device__ float g_Sagg[N_MAX * HD];    // segment_sum(efeat)

// vectorized float4 reduction to global memory (sm_90+)
__device__ __forceinline__ void red_add_v4(float* p, float x, float y, float z, float w) {
    asm volatile("red.global.add.v4.f32 [%0], {%1,%2,%3,%4};"
                 :: "l"(p), "f"(x), "f"(y), "f"(z), "f"(w) : "memory");
}
__device__ __forceinline__ void red_add_f32(float* p, float x) {
    asm volatile("red.global.add.f32 [%0], %1;" :: "l"(p), "f"(x) : "memory");
}

__device__ __forceinline__ unsigned f2tf(float f) {
    unsigned r;
    asm("cvt.rna.tf32.f32 %0, %1;" : "=r"(r) : "f"(f));
    return r;
}

__device__ __forceinline__ float leaky02(float x) { return x > 0.f ? x : 0.2f * x; }

// ---------------- GEMM via tf32 mma.sync: 128x128 block, 8 warps --------------
// mode 0: out = A@W  (+ el/er head reductions)
// mode 1: out[row] = out[row]*invden + bias + hf[row]*inv1 + (A@W)[row]*invm + b_e*gate
#define KC 32
__global__ __launch_bounds__(256, 2)
void gemm_tc_kernel(const float* __restrict__ A, const float* __restrict__ W,
                    float* __restrict__ out, int nrows, int mode,
                    const float4* __restrict__ al4, const float4* __restrict__ ar4,
                    const float4* __restrict__ bias4, const float4* __restrict__ be4) {
    __shared__ __align__(16) float smem[KC * 136 + 128 * 36];   // 35.8 KB
    float (*Ws)[136] = reinterpret_cast<float(*)[136]>(smem);          // tf32 bits
    float (*As)[36]  = reinterpret_cast<float(*)[36]>(smem + KC * 136);
    float (*Cs)[36]  = reinterpret_cast<float(*)[36]>(smem);           // epilogue reuse

    int tid = threadIdx.x;
    int w = tid >> 5, lane = tid & 31;
    int g = lane >> 2, tg = lane & 3;
    int rbase = blockIdx.x * 128;

    float acc[16][4];
#pragma unroll
    for (int j = 0; j < 16; j++)
#pragma unroll
        for (int i = 0; i < 4; i++) acc[j][i] = 0.f;

    for (int kc = 0; kc < 4; kc++) {
        // W chunk rows kc*32..+31 (cvt to tf32 at store)
#pragma unroll
        for (int i = 0; i < 4; i++) {
            int lin = i * 256 + tid;
            int r = lin >> 5, c4 = lin & 31;
            float4 v = ((const float4*)W)[(kc * 32 + r) * 32 + c4];
            Ws[r][c4 * 4 + 0] = __uint_as_float(f2tf(v.x));
            Ws[r][c4 * 4 + 1] = __uint_as_float(f2tf(v.y));
            Ws[r][c4 * 4 + 2] = __uint_as_float(f2tf(v.z));
            Ws[r][c4 * 4 + 3] = __uint_as_float(f2tf(v.w));
        }
        // A chunk: 128 rows x 32 k
#pragma unroll
        for (int i = 0; i < 4; i++) {
            int lin = i * 256 + tid;
            int r = lin >> 3, k4 = lin & 7;
            int row = rbase + r;
            float4 v = (row < nrows) ? ((const float4*)A)[(size_t)row * 32 + kc * 8 + k4]
                                     : make_float4(0.f, 0.f, 0.f, 0.f);
            As[r][k4 * 4 + 0] = __uint_as_float(f2tf(v.x));
            As[r][k4 * 4 + 1] = __uint_as_float(f2tf(v.y));
            As[r][k4 * 4 + 2] = __uint_as_float(f2tf(v.z));
            As[r][k4 * 4 + 3] = __uint_as_float(f2tf(v.w));
        }
        __syncthreads();
#pragma unroll
        for (int ks = 0; ks < 4; ks++) {
            int kb = ks * 8;
            unsigned a0 = __float_as_uint(As[16 * w + g][kb + tg]);
            unsigned a1 = __float_as_uint(As[16 * w + g + 8][kb + tg]);
            unsigned a2 = __float_as_uint(As[16 * w + g][kb + tg + 4]);
            unsigned a3 = __float_as_uint(As[16 * w + g + 8][kb + tg + 4]);
#pragma unroll
            for (int j = 0; j < 16; j++) {
                unsigned b0 = __float_as_uint(Ws[kb + tg][8 * j + g]);
                unsigned b1 = __float_as_uint(Ws[kb + tg + 4][8 * j + g]);
                asm volatile(
                    "mma.sync.aligned.m16n8k8.row.col.f32.tf32.tf32.f32 "
                    "{%0,%1,%2,%3},{%4,%5,%6,%7},{%8,%9},{%0,%1,%2,%3};"
                    : "+f"(acc[j][0]), "+f"(acc[j][1]), "+f"(acc[j][2]), "+f"(acc[j][3])
                    : "r"(a0), "r"(a1), "r"(a2), "r"(a3), "r"(b0), "r"(b1));
            }
        }
        __syncthreads();
    }

    // ---- epilogue: stage C through smem in 4 column chunks of 32 ----
    for (int c = 0; c < 4; c++) {
#pragma unroll
        for (int jj = 0; jj < 4; jj++) {
            int j = 4 * c + jj;
            int col = 8 * jj + 2 * tg;
            int row = 16 * w + g;
            Cs[row][col]     = acc[j][0];
            Cs[row][col + 1] = acc[j][1];
            Cs[row + 8][col]     = acc[j][2];
            Cs[row + 8][col + 1] = acc[j][3];
        }
        __syncthreads();

        int row = tid >> 1, half = tid & 1;
        int head = 2 * c + half;
        int r = rbase + row;
        int gc = 32 * c + 16 * half;          // global col of this thread's 16-col head slice
        float cv[16];
#pragma unroll
        for (int i = 0; i < 16; i++) cv[i] = Cs[row][16 * half + i];

        if (r < nrows) {
            if (mode == 0) {
#pragma unroll
                for (int i = 0; i < 4; i++)
                    *(float4*)&out[(size_t)r * 128 + gc + 4 * i] =
                        make_float4(cv[4 * i], cv[4 * i + 1], cv[4 * i + 2], cv[4 * i + 3]);
                float pl = 0.f, pr = 0.f;
#pragma unroll
                for (int i = 0; i < 4; i++) {
                    float4 a = al4[4 * head + i], b = ar4[4 * head + i];
                    pl += cv[4 * i] * a.x + cv[4 * i + 1] * a.y + cv[4 * i + 2] * a.z + cv[4 * i + 3] * a.w;
                    pr += cv[4 * i] * b.x + cv[4 * i + 1] * b.y + cv[4 * i + 2] * b.z + cv[4 * i + 3] * b.w;
                }
                g_el[r * NH + head] = pl;
                g_er[r * NH + head] = pr;
            } else {
                float deg = g_indeg[r];
                float den = g_denom[r * NH + head];
                float invden = den > 0.f ? 1.f / den : 0.f;
                float inv1 = 1.f / (deg + 1.f);
                float invm = 1.f / fmaxf(deg, 1.f);
                float gate = deg > 0.f ? 1.f : 0.f;
#pragma unroll
                for (int i = 0; i < 4; i++) {
                    float4 o  = *(const float4*)&out[(size_t)r * 128 + gc + 4 * i];
                    float4 hh = *(const float4*)&g_hf[(size_t)r * 128 + gc + 4 * i];
                    float4 b  = bias4[8 * c + 4 * half + i];
                    float4 be = be4[8 * c + 4 * half + i];
                    o.x = o.x * invden + b.x + hh.x * inv1 + cv[4 * i + 0] * invm + be.x * gate;
                    o.y = o.y * invden + b.y + hh.y * inv1 + cv[4 * i + 1] * invm + be.y * gate;
                    o.z = o.z * invden + b.z + hh.z * inv1 + cv[4 * i + 2] * invm + be.z * gate;
                    o.w = o.w * invden + b.w + hh.w * inv1 + cv[4 * i + 3] * invm + be.w * gate;
                    *(float4*)&out[(size_t)r * 128 + gc + 4 * i] = o;
                }
            }
        }
        __syncthreads();
    }
}

// ---------------- fused edge pass (8 edges per warp, all loads batched):
//   Sagg[dst] += efeat[e];  indeg[dst]++
//   ex = exp(leaky(el[src]+er[dst])); denom[dst] += ex; out[dst] += ex*hf[src]
// (softmax max-shift dropped: scores are O(1); division deferred to gemm2 epilogue)
#define EPB 8
__global__ __launch_bounds__(256)
void edge_kernel(const float4* __restrict__ efeat4,
                 const int* __restrict__ src, const int* __restrict__ dst,
                 float* __restrict__ out, int E) {
    int w = (blockIdx.x * blockDim.x + threadIdx.x) >> 5;
    int lane = threadIdx.x & 31;
    int e0 = w * EPB;
    if (e0 >= E) return;
    int ne = E - e0; if (ne > EPB) ne = EPB;

    int sE[EPB], dE[EPB];
#pragma unroll
    for (int q = 0; q < EPB; q++) {
        int e = e0 + (q < ne ? q : ne - 1);
        sE[q] = src[e]; dE[q] = dst[e];
    }
    float4 ef[EPB], hv[EPB];
#pragma unroll
    for (int q = 0; q < EPB; q++)
        ef[q] = __ldcs(&efeat4[(size_t)(e0 + (q < ne ? q : ne - 1)) * 32 + lane]);
#pragma unroll
    for (int q = 0; q < EPB; q++)
        hv[q] = ((const float4*)g_hf)[(size_t)sE[q] * 32 + lane];

    int hh = lane & 7;
    float exv[EPB];
#pragma unroll
    for (int q = 0; q < EPB; q++) {
        float ev = __ldg(&g_el[sE[q] * NH + hh]) + __ldg(&g_er[dE[q] * NH + hh]);
        exv[q] = __expf(leaky02(ev));
    }

    if (lane == 0) {
#pragma unroll
        for (int q = 0; q < EPB; q++)
            if (q < ne) red_add_f32(&g_indeg[dE[q]], 1.0f);
    }
#pragma unroll
    for (int q = 0; q < EPB; q++) {
        if (q < ne) {
            red_add_v4(&g_Sagg[(size_t)dE[q] * 128 + lane * 4],
                       ef[q].x, ef[q].y, ef[q].z, ef[q].w);
            if (lane < 8) red_add_f32(&g_denom[dE[q] * NH + hh], exv[q]);
            float a = __shfl_sync(0xffffffffu, exv[q], lane >> 2);
            red_add_v4(&out[(size_t)dE[q] * 128 + lane * 4],
                       a * hv[q].x, a * hv[q].y, a * hv[q].z, a * hv[q].w);
        }
    }
}

extern "C" void kernel_launch(void* const* d_in, const int* in_sizes, int n_in,
                              void* d_out, int out_size) {
    const float* nfeat  = (const float*)d_in[0];
    const float* efeat  = (const float*)d_in[1];
    const int*   src    = (const int*)d_in[2];
    const int*   dst    = (const int*)d_in[3];
    const float* W_fc   = (const float*)d_in[4];
    const float* attn_l = (const float*)d_in[5];
    const float* attn_r = (const float*)d_in[6];
    const float* bias   = (const float*)d_in[7];
    const float* W_e    = (const float*)d_in[8];
    const float* b_e    = (const float*)d_in[9];
    float* out = (float*)d_out;

    int N = in_sizes[0] / 128;
    int E = in_sizes[2];

    float* d_hf;    cudaGetSymbolAddress((void**)&d_hf,    g_hf);
    float* d_Sagg;  cudaGetSymbolAddress((void**)&d_Sagg,  g_Sagg);
    float* d_denom; cudaGetSymbolAddress((void**)&d_denom, g_denom);
    float* d_indeg; cudaGetSymbolAddress((void**)&d_indeg, g_indeg);

    cudaMemsetAsync(out,     0, (size_t)N * HD * sizeof(float));
    cudaMemsetAsync(d_Sagg,  0, (size_t)N * HD * sizeof(float));
    cudaMemsetAsync(d_denom, 0, (size_t)N * NH * sizeof(float));
    cudaMemsetAsync(d_indeg, 0, (size_t)N * sizeof(float));

    gemm_tc_kernel<<<(N + 127) / 128, 256>>>(nfeat, W_fc, d_hf, N, 0,
                                             (const float4*)attn_l, (const float4*)attn_r,
                                             nullptr, nullptr);

    int warps = (E + EPB - 1) / EPB;
    edge_kernel<<<(warps * 32 + 255) / 256, 256>>>((const float4*)efeat, src, dst, out, E);

    gemm_tc_kernel<<<(N + 127) / 128, 256>>>(d_Sagg, W_e, out, N, 1,
                                             nullptr, nullptr,
                                             (const float4*)bias, (const float4*)b_e);
}